// round 1
// baseline (speedup 1.0000x reference)
#include <cuda_runtime.h>
#include <math.h>

// Scratch (no allocations allowed in kernel_launch).
#define MAX_EDGES 100000
#define MAX_PATHS 20000

__device__ float g_scores[MAX_EDGES];
__device__ float g_logits[MAX_PATHS];

// ---------------------------------------------------------------------------
// Kernel 1: s[e] = dot(edge_emb[e, :256], W[:256])
// One warp per edge. Each lane handles 8 contiguous floats (2x float4).
// ---------------------------------------------------------------------------
__global__ void score_kernel(const float* __restrict__ emb,
                             const float* __restrict__ W,
                             float* __restrict__ s,
                             int n_edges) {
    int warp = (blockIdx.x * blockDim.x + threadIdx.x) >> 5;
    int lane = threadIdx.x & 31;
    if (warp >= n_edges) return;

    const float4* e = reinterpret_cast<const float4*>(emb + (size_t)warp * 256);
    const float4* w = reinterpret_cast<const float4*>(W);

    float4 a0 = e[lane * 2];
    float4 a1 = e[lane * 2 + 1];
    float4 w0 = __ldg(&w[lane * 2]);
    float4 w1 = __ldg(&w[lane * 2 + 1]);

    float acc = a0.x * w0.x + a0.y * w0.y + a0.z * w0.z + a0.w * w0.w
              + a1.x * w1.x + a1.y * w1.y + a1.z * w1.z + a1.w * w1.w;

    #pragma unroll
    for (int o = 16; o; o >>= 1)
        acc += __shfl_xor_sync(0xFFFFFFFFu, acc, o);

    if (lane == 0) s[warp] = acc;
}

// ---------------------------------------------------------------------------
// Kernel 2: per-path masked logits via scalar-score gather.
// logit_i = (1/len_i) * sum_{j<len_i} s[paths[i,j]] + b ;  mask==0 -> -1e9
// ---------------------------------------------------------------------------
__global__ void logits_kernel(const int* __restrict__ paths,
                              const int* __restrict__ path_lens,
                              const int* __restrict__ path_mask,
                              const float* __restrict__ s,
                              const float* __restrict__ b,
                              float* __restrict__ logits,
                              int n_paths, int max_len) {
    int i = blockIdx.x * blockDim.x + threadIdx.x;
    if (i >= n_paths) return;

    int len = path_lens[i] + 1;  // reference: lens = path_lens + 1 (1..max_len)
    const int* row = paths + (size_t)i * max_len;

    float sum = 0.0f;
    for (int j = 0; j < len; ++j)
        sum += s[row[j]];

    float logit = sum / (float)len + b[0];
    if (path_mask[i] == 0) logit = -1e9f;
    logits[i] = logit;
}

// ---------------------------------------------------------------------------
// Kernel 3 (single block, 1024 threads):
//  phase 1: argmax over logits (first-index tiebreak, matches jnp.argmax)
//  phase 2: logsumexp -> logprob = logits[p] - max - log(sum exp(. - max))
//  phase 3: z[p] = mean of edge_emb rows of the winning path (256 cols)
// out: [0]=p (as float), [1]=logprob, [2..257]=z[p]
// ---------------------------------------------------------------------------
__global__ void finalize_kernel(const float* __restrict__ logits,
                                int n_paths,
                                const float* __restrict__ emb,
                                const int* __restrict__ paths,
                                const int* __restrict__ path_lens,
                                int max_len,
                                float* __restrict__ out) {
    __shared__ float smax[1024];
    __shared__ int   sidx[1024];
    __shared__ float ssum[1024];

    int t = threadIdx.x;

    // --- argmax with first-occurrence tiebreak ---
    float best = -INFINITY;
    int bidx = n_paths;  // sentinel (larger than any real index)
    for (int i = t; i < n_paths; i += 1024) {
        float v = logits[i];
        if (v > best || (v == best && i < bidx)) { best = v; bidx = i; }
    }
    smax[t] = best;
    sidx[t] = bidx;
    __syncthreads();
    #pragma unroll
    for (int o = 512; o; o >>= 1) {
        if (t < o) {
            float v = smax[t + o];
            int   j = sidx[t + o];
            if (v > smax[t] || (v == smax[t] && j < sidx[t])) {
                smax[t] = v; sidx[t] = j;
            }
        }
        __syncthreads();
    }
    float maxv = smax[0];
    int p = sidx[0];

    // --- logsumexp ---
    float ls = 0.0f;
    for (int i = t; i < n_paths; i += 1024)
        ls += expf(logits[i] - maxv);
    ssum[t] = ls;
    __syncthreads();
    #pragma unroll
    for (int o = 512; o; o >>= 1) {
        if (t < o) ssum[t] += ssum[t + o];
        __syncthreads();
    }

    if (t == 0) {
        out[0] = (float)p;
        out[1] = (logits[p] - maxv) - logf(ssum[0]);
    }

    // --- z[p]: per-column ragged mean for the winning path ---
    if (t < 256) {
        int len = path_lens[p] + 1;
        const int* row = paths + (size_t)p * max_len;
        float acc = 0.0f;
        for (int j = 0; j < len; ++j) {
            int e = row[j];
            acc += emb[(size_t)e * 256 + t];
        }
        out[2 + t] = acc / (float)len;
    }
}

// ---------------------------------------------------------------------------
// Launch
// Inputs (metadata order): edge_emb f32[100000,256], paths i32[20000,16],
//   path_lens i32[20000], path_mask i32[20000], W f32[1,256], b f32[1],
//   deterministic i32[1]
// ---------------------------------------------------------------------------
extern "C" void kernel_launch(void* const* d_in, const int* in_sizes, int n_in,
                              void* d_out, int out_size) {
    const float* edge_emb  = (const float*)d_in[0];
    const int*   paths     = (const int*)d_in[1];
    const int*   path_lens = (const int*)d_in[2];
    const int*   path_mask = (const int*)d_in[3];
    const float* W         = (const float*)d_in[4];
    const float* b         = (const float*)d_in[5];

    int hidden  = in_sizes[4];              // 256
    int n_edges = in_sizes[0] / hidden;     // 100000
    int n_paths = in_sizes[2];              // 20000
    int max_len = in_sizes[1] / n_paths;    // 16

    float* out = (float*)d_out;

    float* scores; cudaGetSymbolAddress((void**)&scores, g_scores);
    float* logits; cudaGetSymbolAddress((void**)&logits, g_logits);

    // Kernel 1: one warp per edge (8 warps / 256-thread block)
    {
        int warps_per_block = 8;
        int blocks = (n_edges + warps_per_block - 1) / warps_per_block;
        score_kernel<<<blocks, warps_per_block * 32>>>(edge_emb, W, scores, n_edges);
    }

    // Kernel 2: one thread per path
    {
        int threads = 256;
        int blocks = (n_paths + threads - 1) / threads;
        logits_kernel<<<blocks, threads>>>(paths, path_lens, path_mask,
                                           scores, b, logits, n_paths, max_len);
    }

    // Kernel 3: single-block reduce + winner embedding mean
    finalize_kernel<<<1, 1024>>>(logits, n_paths, edge_emb, paths, path_lens,
                                 max_len, out);
}

// round 2
// speedup vs baseline: 1.3236x; 1.3236x over previous
#include <cuda_runtime.h>
#include <math.h>

#define MAX_EDGES 100000
#define MAX_PART  256   // >= ceil(20000/256) = 79

__device__ float g_scores[MAX_EDGES];
__device__ float g_pmax[MAX_PART];
__device__ int   g_pidx[MAX_PART];
__device__ float g_psum[MAX_PART];

// ---------------------------------------------------------------------------
// Kernel 1: s[e] = dot(edge_emb[e,:256], W)
// One warp per TWO edges: 4 independent LDG.128 per lane -> higher MLP,
// reduction/store cost amortized over 2 KB instead of 1 KB.
// ---------------------------------------------------------------------------
__global__ void __launch_bounds__(256) score_kernel(
        const float* __restrict__ emb,
        const float* __restrict__ W,
        float* __restrict__ s,
        int n_edges) {
    int warp = (blockIdx.x * blockDim.x + threadIdx.x) >> 5;
    int lane = threadIdx.x & 31;
    int e0 = warp * 2;
    if (e0 >= n_edges) return;

    const float4* w = reinterpret_cast<const float4*>(W);
    float4 w0 = __ldg(&w[lane * 2]);
    float4 w1 = __ldg(&w[lane * 2 + 1]);

    const float4* p0 = reinterpret_cast<const float4*>(emb + (size_t)e0 * 256);
    const float4* p1 = p0 + 64;  // next edge row (256 floats = 64 float4)

    float4 a0 = p0[lane * 2];
    float4 a1 = p0[lane * 2 + 1];
    float4 b0 = p1[lane * 2];
    float4 b1 = p1[lane * 2 + 1];

    float accA = a0.x * w0.x + a0.y * w0.y + a0.z * w0.z + a0.w * w0.w
               + a1.x * w1.x + a1.y * w1.y + a1.z * w1.z + a1.w * w1.w;
    float accB = b0.x * w0.x + b0.y * w0.y + b0.z * w0.z + b0.w * w0.w
               + b1.x * w1.x + b1.y * w1.y + b1.z * w1.z + b1.w * w1.w;

    #pragma unroll
    for (int o = 16; o; o >>= 1) {
        accA += __shfl_xor_sync(0xFFFFFFFFu, accA, o);
        accB += __shfl_xor_sync(0xFFFFFFFFu, accB, o);
    }

    if (lane == 0) {
        s[e0] = accA;
        if (e0 + 1 < n_edges) s[e0 + 1] = accB;
    }
}

// ---------------------------------------------------------------------------
// Kernel 2: per-path masked logit + per-block flash-softmax partials.
// Each thread: one path. Block reduces (max, first-argmax) then local
// sum of exp(l - blockmax). No global logits array needed.
// ---------------------------------------------------------------------------
__global__ void __launch_bounds__(256) logits_partial_kernel(
        const int* __restrict__ paths,
        const int* __restrict__ path_lens,
        const int* __restrict__ path_mask,
        const float* __restrict__ s,
        const float* __restrict__ b,
        int n_paths, int max_len) {
    __shared__ float smax[256];
    __shared__ int   sidx[256];
    __shared__ float ssum[256];

    int t = threadIdx.x;
    int i = blockIdx.x * 256 + t;

    float logit = -INFINITY;
    int   idx   = 0x7FFFFFFF;   // sentinel for invalid threads
    if (i < n_paths) {
        int len = path_lens[i] + 1;
        const int4* row = reinterpret_cast<const int4*>(paths + (size_t)i * max_len);
        int4 r0 = row[0], r1 = row[1], r2 = row[2], r3 = row[3];
        int e[16] = { r0.x, r0.y, r0.z, r0.w, r1.x, r1.y, r1.z, r1.w,
                      r2.x, r2.y, r2.z, r2.w, r3.x, r3.y, r3.z, r3.w };
        float sum = 0.0f;
        #pragma unroll
        for (int j = 0; j < 16; ++j)
            if (j < len) sum += s[e[j]];
        logit = sum / (float)len + b[0];
        if (path_mask[i] == 0) logit = -1e9f;
        idx = i;
    }

    // block argmax (first-occurrence tiebreak)
    smax[t] = logit; sidx[t] = idx;
    __syncthreads();
    #pragma unroll
    for (int o = 128; o; o >>= 1) {
        if (t < o) {
            float v = smax[t + o]; int j = sidx[t + o];
            if (v > smax[t] || (v == smax[t] && j < sidx[t])) {
                smax[t] = v; sidx[t] = j;
            }
        }
        __syncthreads();
    }
    float bm = smax[0];

    // local sumexp relative to block max
    float es = (i < n_paths) ? expf(logit - bm) : 0.0f;
    ssum[t] = es;
    __syncthreads();
    #pragma unroll
    for (int o = 128; o; o >>= 1) {
        if (t < o) ssum[t] += ssum[t + o];
        __syncthreads();
    }

    if (t == 0) {
        g_pmax[blockIdx.x] = bm;
        g_pidx[blockIdx.x] = sidx[0];
        g_psum[blockIdx.x] = ssum[0];
    }
}

// ---------------------------------------------------------------------------
// Kernel 3 (single block, 256 threads): combine <=256 partials, then z[p].
// logits[p] == global max M  =>  logprob = -log(sum exp(l - M)).
// ---------------------------------------------------------------------------
__global__ void __launch_bounds__(256) finalize_kernel(
        int n_part,
        const float* __restrict__ emb,
        const int* __restrict__ paths,
        const int* __restrict__ path_lens,
        int max_len,
        float* __restrict__ out) {
    __shared__ float smax[256];
    __shared__ int   sidx[256];
    __shared__ float ssum[256];
    __shared__ float sM;
    __shared__ int   sp;

    int t = threadIdx.x;
    float m = (t < n_part) ? g_pmax[t] : -INFINITY;
    int   j = (t < n_part) ? g_pidx[t] : 0x7FFFFFFF;

    smax[t] = m; sidx[t] = j;
    __syncthreads();
    #pragma unroll
    for (int o = 128; o; o >>= 1) {
        if (t < o) {
            float v = smax[t + o]; int k = sidx[t + o];
            if (v > smax[t] || (v == smax[t] && k < sidx[t])) {
                smax[t] = v; sidx[t] = k;
            }
        }
        __syncthreads();
    }
    if (t == 0) { sM = smax[0]; sp = sidx[0]; }
    __syncthreads();
    float M = sM;
    int p = sp;

    // total sumexp: rescale each block's partial
    float es = (t < n_part) ? g_psum[t] * expf(g_pmax[t] - M) : 0.0f;
    ssum[t] = es;
    __syncthreads();
    #pragma unroll
    for (int o = 128; o; o >>= 1) {
        if (t < o) ssum[t] += ssum[t + o];
        __syncthreads();
    }

    if (t == 0) {
        out[0] = (float)p;
        out[1] = -logf(ssum[0]);   // logits[p] - M == 0
    }

    // z[p]: per-column ragged mean of the winning path (256 columns)
    {
        int len = path_lens[p] + 1;
        const int* row = paths + (size_t)p * max_len;
        float acc = 0.0f;
        for (int k = 0; k < len; ++k)
            acc += emb[(size_t)row[k] * 256 + t];
        out[2 + t] = acc / (float)len;
    }
}

// ---------------------------------------------------------------------------
// Launch
// Inputs: edge_emb f32[100000,256], paths i32[20000,16], path_lens i32[20000],
//         path_mask i32[20000], W f32[1,256], b f32[1], deterministic i32[1]
// ---------------------------------------------------------------------------
extern "C" void kernel_launch(void* const* d_in, const int* in_sizes, int n_in,
                              void* d_out, int out_size) {
    const float* edge_emb  = (const float*)d_in[0];
    const int*   paths     = (const int*)d_in[1];
    const int*   path_lens = (const int*)d_in[2];
    const int*   path_mask = (const int*)d_in[3];
    const float* W         = (const float*)d_in[4];
    const float* b         = (const float*)d_in[5];

    int hidden  = in_sizes[4];              // 256
    int n_edges = in_sizes[0] / hidden;     // 100000
    int n_paths = in_sizes[2];              // 20000
    int max_len = in_sizes[1] / n_paths;    // 16

    float* out = (float*)d_out;

    float* scores; cudaGetSymbolAddress((void**)&scores, g_scores);

    // K1: 2 edges per warp, 8 warps per block
    {
        int edges_per_block = 16;  // 8 warps * 2 edges
        int blocks = (n_edges + edges_per_block - 1) / edges_per_block;
        score_kernel<<<blocks, 256>>>(edge_emb, W, scores, n_edges);
    }

    // K2: one thread per path, per-block softmax partials
    int nb2 = (n_paths + 255) / 256;
    logits_partial_kernel<<<nb2, 256>>>(paths, path_lens, path_mask,
                                        scores, b, n_paths, max_len);

    // K3: combine partials + winner embedding mean
    finalize_kernel<<<1, 256>>>(nb2, edge_emb, paths, path_lens, max_len, out);
}